// round 4
// baseline (speedup 1.0000x reference)
#include <cuda_runtime.h>
#include <math_constants.h>

__device__ float        g_sum;
__device__ float        g_cnt;
__device__ unsigned int g_ticket;

#define ROWW 132   // padded row stride in floats: stride%32==4 -> conflict-free LDS.128

extern __shared__ float semb[];   // 256 * ROWW floats = 135168 B (dynamic)

__global__ void __launch_bounds__(256, 1)
triplet_fused(const float* __restrict__ emb,
              const int* __restrict__ labraw,
              float* __restrict__ out) {
    __shared__ float dnegS[256];   // d[i,j] if j "negative" (diff label OR j==i), else -inf
    __shared__ float dkS[256];
    __shared__ int   labsh[256];
    __shared__ int   s_plist[256];
    __shared__ float s_wmax[8];
    __shared__ int   s_is64;
    __shared__ int   s_npos;
    __shared__ float s_bsum;

    const int i    = blockIdx.x;
    const int t    = threadIdx.x;
    const int lane = t & 31;
    const int w    = t >> 5;

    if (t == 0) { s_is64 = 1; s_npos = 0; s_bsum = 0.f; }
    __syncthreads();

    // label dtype detection: int64 labels in [0,16) have zero high words.
    // Reads only the first 1KB (in-bounds for both int32[256] and int64[256]).
    if (t < 128 && labraw[2 * t + 1] != 0) s_is64 = 0;   // benign race: all store 0

    // ---- coalesced staging of emb [256x128] into padded smem rows ----
    const float4* src = (const float4*)emb;
    #pragma unroll
    for (int k = 0; k < 32; k++) {
        int   idx4 = k * 256 + t;          // consecutive lanes -> consecutive 16B
        float4 v   = src[idx4];
        int   r    = idx4 >> 5;            // row (32 float4 per row)
        int   c4   = idx4 & 31;
        *(float4*)(semb + r * ROWW + c4 * 4) = v;
    }
    __syncthreads();

    labsh[t] = s_is64 ? labraw[2 * t] : labraw[t];
    __syncthreads();

    // ---- phase 1: d[i, t] from smem (conflict-free LDS.128) ----
    const float* rowT = semb + t * ROWW;
    const float* rowI = semb + i * ROWW;
    float dot = 0.f, nj = 0.f, ni = 0.f;
    #pragma unroll
    for (int c = 0; c < 128; c += 4) {
        float4 a = *(const float4*)(rowT + c);
        float4 b = *(const float4*)(rowI + c);   // broadcast
        dot += a.x * b.x + a.y * b.y + a.z * b.z + a.w * b.w;
        nj  += a.x * a.x + a.y * a.y + a.z * a.z + a.w * a.w;
        ni  += b.x * b.x + b.y * b.y + b.z * b.z + b.w * b.w;
    }
    const float dk = sqrtf(fmaxf(ni + nj - 2.f * dot, 1e-4f));

    const int  li    = labsh[i];
    const bool neg   = (labsh[t] != li) || (t == i);   // (1 - pos) includes diagonal
    const bool ispos = !neg;
    const float dn   = neg ? dk : -CUDART_INF_F;
    dnegS[t] = dn;
    dkS[t]   = dk;
    if (ispos) { int p = atomicAdd(&s_npos, 1); s_plist[p] = t; }

    // ---- block-wide maxNeg (independent of k) ----
    float m = dn;
    #pragma unroll
    for (int off = 16; off; off >>= 1) m = fmaxf(m, __shfl_xor_sync(~0u, m, off));
    if (lane == 0) s_wmax[w] = m;
    __syncthreads();
    if (t == 0) {
        float mm = s_wmax[0];
        #pragma unroll
        for (int q = 1; q < 8; q++) mm = fmaxf(mm, s_wmax[q]);
        s_wmax[0] = mm;
    }
    __syncthreads();
    const float maxNeg = s_wmax[0];
    const int   np     = s_npos;

    // ---- phase 2: warp-cooperative semi-hard scan, one positive per warp-slot ----
    float wsum = 0.f;
    for (int p = w; p < np; p += 8) {
        int   k   = s_plist[p];
        float dkk = dkS[k];
        float mg  = CUDART_INF_F;          // min over negatives with d > dkk
        #pragma unroll
        for (int q = 0; q < 8; q++) {
            float dj = dnegS[lane + 32 * q];   // stride-32 words: one bank per lane
            mg = fminf(mg, dj > dkk ? dj : CUDART_INF_F);
        }
        #pragma unroll
        for (int off = 16; off; off >>= 1) mg = fminf(mg, __shfl_xor_sync(~0u, mg, off));
        float v = (mg < CUDART_INF_F) ? (dkk - mg)       // semi-hard exists
                                      : (dkk - maxNeg);  // fallback: easiest negative
        wsum += fmaxf(v + 1.0f, 0.f);                    // relu(semi_hard + MARGIN)
    }
    if (lane == 0 && wsum != 0.f) atomicAdd(&s_bsum, wsum);
    __syncthreads();

    // ---- last-block-done epilogue (replaces second kernel) ----
    if (t == 0) {
        atomicAdd(&g_sum, s_bsum);
        atomicAdd(&g_cnt, (float)np);
        __threadfence();
        unsigned tk = atomicAdd(&g_ticket, 1u);
        if (tk == gridDim.x - 1) {
            __threadfence();
            float s = atomicAdd(&g_sum, 0.f);
            float c = atomicAdd(&g_cnt, 0.f);
            out[0] = s / c;
            // reset for next graph replay
            g_sum = 0.f;
            g_cnt = 0.f;
            __threadfence();
            g_ticket = 0u;
        }
    }
}

extern "C" void kernel_launch(void* const* d_in, const int* in_sizes, int n_in,
                              void* d_out, int out_size) {
    const float* emb    = (const float*)d_in[0];   // [256, 128] float32
    const int*   labraw = (const int*)d_in[1];     // [256] labels (int64/int32 detected)
    float* out = (float*)d_out;

    const int smem = 256 * ROWW * sizeof(float);   // 135168 B
    cudaFuncSetAttribute(triplet_fused, cudaFuncAttributeMaxDynamicSharedMemorySize, smem);
    triplet_fused<<<256, 256, smem>>>(emb, labraw, out);
}

// round 5
// speedup vs baseline: 1.6375x; 1.6375x over previous
#include <cuda_runtime.h>
#include <math_constants.h>

#define NA    4     // anchors per block
#define GRID  64    // 64 * 4 = 256 anchors, single wave on 148+ SMs
#define ROWW  132   // padded row stride (floats): conflict-free LDS.128

__device__ float        g_sum;
__device__ float        g_cnt;
__device__ unsigned int g_ticket;

extern __shared__ float semb[];   // 256 * ROWW floats = 135168 B (dynamic)

__global__ void __launch_bounds__(256, 1)
triplet_fused(const float* __restrict__ emb,
              const int* __restrict__ labraw,
              float* __restrict__ out) {
    __shared__ float dkS[NA][260];     // d[ia, j] rows (260%32==4 -> conflict-free)
    __shared__ float normS[256];
    __shared__ int   labsh[256];
    __shared__ int   s_plist[NA * 256];
    __shared__ float s_wmax[NA][8];
    __shared__ float s_maxneg[NA];
    __shared__ int   s_is64;
    __shared__ int   s_npos;
    __shared__ float s_bsum;

    const int t    = threadIdx.x;
    const int lane = t & 31;
    const int w    = t >> 5;
    const int ib   = blockIdx.x * NA;   // first anchor of this block

    if (t == 0) { s_is64 = 1; s_npos = 0; s_bsum = 0.f; }
    __syncthreads();

    // label dtype detect: int64 labels in [0,16) have zero high words.
    // Touches only the first 1KB — in-bounds for both int32[256] and int64[256].
    if (t < 128 && labraw[2 * t + 1] != 0) s_is64 = 0;   // benign race: all store 0

    // ---- coalesced staging of emb [256x128] into padded smem rows ----
    const float4* src = (const float4*)emb;
    #pragma unroll
    for (int k = 0; k < 32; k++) {
        int    idx4 = k * 256 + t;         // consecutive lanes -> consecutive 16B
        float4 v    = src[idx4];
        int    r    = idx4 >> 5;
        int    c4   = idx4 & 31;
        *(float4*)(semb + r * ROWW + c4 * 4) = v;
    }
    __syncthreads();

    labsh[t] = s_is64 ? labraw[2 * t] : labraw[t];
    __syncthreads();

    // ---- phase 1: 4 distance rows, rowT read ONCE for all 4 anchors ----
    const float* rowT = semb + t * ROWW;
    const float* rowA0 = semb + (ib + 0) * ROWW;
    const float* rowA1 = semb + (ib + 1) * ROWW;
    const float* rowA2 = semb + (ib + 2) * ROWW;
    const float* rowA3 = semb + (ib + 3) * ROWW;

    float dot0 = 0.f, dot1 = 0.f, dot2 = 0.f, dot3 = 0.f, nj = 0.f;
    #pragma unroll
    for (int c = 0; c < 128; c += 4) {
        float4 a  = *(const float4*)(rowT + c);
        float4 b0 = *(const float4*)(rowA0 + c);   // broadcast
        float4 b1 = *(const float4*)(rowA1 + c);
        float4 b2 = *(const float4*)(rowA2 + c);
        float4 b3 = *(const float4*)(rowA3 + c);
        nj   += a.x * a.x  + a.y * a.y  + a.z * a.z  + a.w * a.w;
        dot0 += a.x * b0.x + a.y * b0.y + a.z * b0.z + a.w * b0.w;
        dot1 += a.x * b1.x + a.y * b1.y + a.z * b1.z + a.w * b1.w;
        dot2 += a.x * b2.x + a.y * b2.y + a.z * b2.z + a.w * b2.w;
        dot3 += a.x * b3.x + a.y * b3.y + a.z * b3.z + a.w * b3.w;
    }
    normS[t] = nj;
    __syncthreads();

    float dk[NA];
    float dotv[NA] = {dot0, dot1, dot2, dot3};
    const int labt = labsh[t];
    #pragma unroll
    for (int a = 0; a < NA; a++) {
        const int ia = ib + a;
        dk[a] = sqrtf(fmaxf(normS[ia] + nj - 2.f * dotv[a], 1e-4f));
        dkS[a][t] = dk[a];
        const bool neg = (labt != labsh[ia]) || (t == ia);  // (1 - pos) incl. diagonal
        if (!neg) { int p = atomicAdd(&s_npos, 1); s_plist[p] = (a << 8) | t; }
        // per-anchor block max of negatives (independent shfl chains)
        float m = neg ? dk[a] : -CUDART_INF_F;
        #pragma unroll
        for (int off = 16; off; off >>= 1) m = fmaxf(m, __shfl_xor_sync(~0u, m, off));
        if (lane == 0) s_wmax[a][w] = m;
    }
    __syncthreads();
    if (t < NA) {
        float mm = s_wmax[t][0];
        #pragma unroll
        for (int q = 1; q < 8; q++) mm = fmaxf(mm, s_wmax[t][q]);
        s_maxneg[t] = mm;
    }
    __syncthreads();

    // ---- phase 2: warp-cooperative semi-hard scan over the positives list ----
    const int np = s_npos;
    float wsum = 0.f;
    for (int p = w; p < np; p += 8) {
        const int   e   = s_plist[p];
        const int   a   = e >> 8;
        const int   k   = e & 255;
        const int   ia  = ib + a;
        const int   la  = labsh[ia];
        const float dkk = dkS[a][k];
        float mg = CUDART_INF_F;     // min over negatives with d > dkk
        #pragma unroll
        for (int q = 0; q < 8; q++) {
            const int   j  = lane + 32 * q;          // one bank per lane
            const float dj = dkS[a][j];
            const bool  ng = (labsh[j] != la) || (j == ia);
            mg = fminf(mg, (ng && dj > dkk) ? dj : CUDART_INF_F);
        }
        #pragma unroll
        for (int off = 16; off; off >>= 1) mg = fminf(mg, __shfl_xor_sync(~0u, mg, off));
        float v = (mg < CUDART_INF_F) ? (dkk - mg)          // semi-hard exists
                                      : (dkk - s_maxneg[a]); // fallback: easiest neg
        wsum += fmaxf(v + 1.0f, 0.f);                        // relu(semi_hard + MARGIN)
    }
    if (lane == 0 && wsum != 0.f) atomicAdd(&s_bsum, wsum);
    __syncthreads();

    // ---- last-block-done epilogue (single kernel, no second launch) ----
    if (t == 0) {
        atomicAdd(&g_sum, s_bsum);
        atomicAdd(&g_cnt, (float)np);
        __threadfence();
        unsigned tk = atomicAdd(&g_ticket, 1u);
        if (tk == GRID - 1) {
            __threadfence();
            float s = atomicAdd(&g_sum, 0.f);
            float c = atomicAdd(&g_cnt, 0.f);
            out[0] = s / c;
            g_sum = 0.f;          // reset for next graph replay
            g_cnt = 0.f;
            __threadfence();
            g_ticket = 0u;
        }
    }
}

extern "C" void kernel_launch(void* const* d_in, const int* in_sizes, int n_in,
                              void* d_out, int out_size) {
    const float* emb    = (const float*)d_in[0];   // [256, 128] float32
    const int*   labraw = (const int*)d_in[1];     // [256] labels (int64/int32 detected)
    float* out = (float*)d_out;

    const int smem = 256 * ROWW * sizeof(float);   // 135168 B
    cudaFuncSetAttribute(triplet_fused, cudaFuncAttributeMaxDynamicSharedMemorySize, smem);
    triplet_fused<<<GRID, 256, smem>>>(emb, labraw, out);
}